// round 14
// baseline (speedup 1.0000x reference)
#include <cuda_runtime.h>
#include <cuda_bf16.h>
#include <cstdint>

// Problem constants
#define BB   128
#define HHs  56
#define HWp  3136
#define EE   96
#define NHh  3
#define EHh  32
#define WSw  7
#define NWIN 64
#define WWq  49

typedef unsigned long long ull;
typedef uint32_t u32;

// ---------------- mma.sync / ldmatrix helpers (sm_80+) ----------------
__device__ __forceinline__ u32 smem_u32(const void* p) {
    u32 a;
    asm("{ .reg .u64 t; cvta.to.shared.u64 t, %1; cvt.u32.u64 %0, t; }" : "=r"(a) : "l"(p));
    return a;
}
#define LDSM4(r, addr) \
    asm volatile("ldmatrix.sync.aligned.m8n8.x4.shared.b16 {%0,%1,%2,%3}, [%4];" \
        : "=r"((r)[0]), "=r"((r)[1]), "=r"((r)[2]), "=r"((r)[3]) : "r"(addr))
#define MMA_BF16(d, a, b0, b1) \
    asm volatile("mma.sync.aligned.m16n8k16.row.col.f32.bf16.bf16.f32 " \
        "{%0,%1,%2,%3}, {%4,%5,%6,%7}, {%8,%9}, {%0,%1,%2,%3};" \
        : "+f"((d)[0]), "+f"((d)[1]), "+f"((d)[2]), "+f"((d)[3]) \
        : "r"((a)[0]), "r"((a)[1]), "r"((a)[2]), "r"((a)[3]), "r"(b0), "r"(b1))

// ---------------- scratch (allocation-free rule) ----------------
__device__ float g_qkv[(size_t)BB * HWp * 288];   // identity layout [row][288]
__device__ float g_o[(size_t)BB * HWp * EE];
// bf16 hi/lo weights, row-major [n][k], packed 2 halves per u32
__device__ __align__(16) u32 g_w1h[288 * 48];
__device__ __align__(16) u32 g_w1l[288 * 48];
__device__ __align__(16) u32 g_w2h[96 * 48];
__device__ __align__(16) u32 g_w2l[96 * 48];

// split fp32 pair -> bf16-hi pair, bf16-lo (residual) pair
__device__ __forceinline__ void cvt_pair(float a, float b, u32& hp, u32& lp) {
    __nv_bfloat16 h0 = __float2bfloat16(a), h1 = __float2bfloat16(b);
    float f0 = __bfloat162float(h0), f1 = __bfloat162float(h1);
    __nv_bfloat16 l0 = __float2bfloat16(a - f0), l1 = __float2bfloat16(b - f1);
    hp = (u32)__bfloat16_as_ushort(h0) | ((u32)__bfloat16_as_ushort(h1) << 16);
    lp = (u32)__bfloat16_as_ushort(l0) | ((u32)__bfloat16_as_ushort(l1) << 16);
}

__global__ __launch_bounds__(256) void wconv_kernel(const float* __restrict__ w1,
                                                    const float* __restrict__ w2) {
    int tid0 = blockIdx.x * 256 + threadIdx.x;
    int stride = gridDim.x * 256;
    for (int p = tid0; p < 288 * 48; p += stride) {
        int n = p / 48, kp = (p % 48) * 2;
        float2 v = *(const float2*)(w1 + (size_t)n * 96 + kp);
        u32 hp, lp; cvt_pair(v.x, v.y, hp, lp);
        g_w1h[p] = hp; g_w1l[p] = lp;
    }
    for (int p = tid0; p < 96 * 48; p += stride) {
        int n = p / 48, kp = (p % 48) * 2;
        float2 v = *(const float2*)(w2 + (size_t)n * 96 + kp);
        u32 hp, lp; cvt_pair(v.x, v.y, hp, lp);
        g_w2h[p] = hp; g_w2l[p] = lp;
    }
}

// ---------------- smem layout (GEMM kernels) ----------------
#define SA_STRIDE 208
#define SM_AH   0
#define SM_AL   26624
#define SM_BH   53248
#define SM_BL   73216
#define SM_BIAS 93184
#define SM_SZ   94336

__device__ __forceinline__ void load_A_tile(unsigned char* sm, const float* __restrict__ src,
                                            int row0, int tid) {
    for (int i = tid; i < 3072; i += 256) {
        int row = i / 24, k = (i % 24) * 4;
        float4 v = *(const float4*)(src + (size_t)(row0 + row) * EE + k);
        u32 hp0, lp0, hp1, lp1;
        cvt_pair(v.x, v.y, hp0, lp0);
        cvt_pair(v.z, v.w, hp1, lp1);
        u32 off = (u32)row * SA_STRIDE + (u32)k * 2;
        *(uint2*)(sm + SM_AH + off) = make_uint2(hp0, hp1);
        *(uint2*)(sm + SM_AL + off) = make_uint2(lp0, lp1);
    }
}
__device__ __forceinline__ void load_B_tile(unsigned char* sm, const u32* wh, const u32* wl,
                                            int tid) {
    for (int i = tid; i < 1152; i += 256) {
        int row = i / 12, c4 = i % 12;
        *(float4*)(sm + SM_BH + (u32)row * SA_STRIDE + c4 * 16) = ((const float4*)(wh + (size_t)row * 48))[c4];
        *(float4*)(sm + SM_BL + (u32)row * SA_STRIDE + c4 * 16) = ((const float4*)(wl + (size_t)row * 48))[c4];
    }
}

// 3-term bf16 compensated mainloop, TERM-MAJOR ordering: consecutive MMAs hit
// different accumulators (12-way ILP) instead of a 3-deep RAW chain.
__device__ __forceinline__ void mma_slab(u32 aaddrH, u32 aaddrL, u32 baddrH, u32 baddrL,
                                         float d[12][4]) {
#pragma unroll
    for (int i = 0; i < 12; i++)
#pragma unroll
        for (int j = 0; j < 4; j++) d[i][j] = 0.f;
#pragma unroll
    for (int ks = 0; ks < 6; ks++) {
        u32 ah[4], al[4];
        LDSM4(ah, aaddrH + ks * 32);
        LDSM4(al, aaddrL + ks * 32);
        // term 1: Ah * Bh
#pragma unroll
        for (int np = 0; np < 6; np++) {
            u32 bh[4];
            LDSM4(bh, baddrH + (u32)np * 16 * SA_STRIDE + ks * 32);
            MMA_BF16(d[2 * np],     ah, bh[0], bh[1]);
            MMA_BF16(d[2 * np + 1], ah, bh[2], bh[3]);
        }
        // term 2: Ah * Bl
#pragma unroll
        for (int np = 0; np < 6; np++) {
            u32 bl[4];
            LDSM4(bl, baddrL + (u32)np * 16 * SA_STRIDE + ks * 32);
            MMA_BF16(d[2 * np],     ah, bl[0], bl[1]);
            MMA_BF16(d[2 * np + 1], ah, bl[2], bl[3]);
        }
        // term 3: Al * Bh
#pragma unroll
        for (int np = 0; np < 6; np++) {
            u32 bh[4];
            LDSM4(bh, baddrH + (u32)np * 16 * SA_STRIDE + ks * 32);
            MMA_BF16(d[2 * np],     al, bh[0], bh[1]);
            MMA_BF16(d[2 * np + 1], al, bh[2], bh[3]);
        }
    }
}

// ---------------------------------------------------------------------------
// Kernel 1: qkv GEMM, 3 slabs per CTA. grid=3136.
// ---------------------------------------------------------------------------
__global__ __launch_bounds__(256) void qkv_mma(const float* __restrict__ x,
                                               const float* __restrict__ b1) {
    extern __shared__ unsigned char sm[];
    const u32 sbase = smem_u32(sm);
    const int tid = threadIdx.x, wid = tid >> 5, lane = tid & 31;
    const int row0 = blockIdx.x * 128;

    for (int i = tid; i < 288; i += 256) *(float*)(sm + SM_BIAS + i * 4) = b1[i];
    load_A_tile(sm, x, row0, tid);

    const int m0 = wid * 16;
    const u32 a_row = (u32)(m0 + (lane & 7) + ((lane >> 3) & 1) * 8);
    const u32 a_k   = (u32)((lane >> 4) * 8);
    const u32 aaddrH = sbase + SM_AH + a_row * SA_STRIDE + a_k * 2;
    const u32 aaddrL = sbase + SM_AL + a_row * SA_STRIDE + a_k * 2;
    const u32 b_row = (u32)((lane & 7) + ((lane >= 16) ? 8 : 0));
    const u32 b_k   = (u32)(((lane >> 3) & 1) * 8);
    const u32 baddrH = sbase + SM_BH + b_row * SA_STRIDE + b_k * 2;
    const u32 baddrL = sbase + SM_BL + b_row * SA_STRIDE + b_k * 2;
    const int crow0 = m0 + lane / 4;
    const int ccol  = 2 * (lane & 3);

#pragma unroll
    for (int nb = 0; nb < 3; nb++) {
        __syncthreads();
        load_B_tile(sm, g_w1h + (size_t)nb * 4608, g_w1l + (size_t)nb * 4608, tid);
        __syncthreads();

        float d[12][4];
        mma_slab(aaddrH, aaddrL, baddrH, baddrL, d);

        float* dst0 = g_qkv + (size_t)(row0 + crow0) * 288 + nb * 96;
        float* dst1 = g_qkv + (size_t)(row0 + crow0 + 8) * 288 + nb * 96;
#pragma unroll
        for (int nc = 0; nc < 12; nc++) {
            int n = nc * 8 + ccol;
            float2 bv = *(const float2*)(sm + SM_BIAS + (nb * 96 + n) * 4);
            *(float2*)(dst0 + n) = make_float2(d[nc][0] + bv.x, d[nc][1] + bv.y);
            *(float2*)(dst1 + n) = make_float2(d[nc][2] + bv.x, d[nc][3] + bv.y);
        }
    }
}

// ---------------------------------------------------------------------------
// Kernel 3: proj GEMM. grid=3136.
// ---------------------------------------------------------------------------
__global__ __launch_bounds__(256) void proj_mma(const float* __restrict__ b2,
                                                float* __restrict__ out) {
    extern __shared__ unsigned char sm[];
    const u32 sbase = smem_u32(sm);
    const int tid = threadIdx.x, wid = tid >> 5, lane = tid & 31;
    const int row0 = blockIdx.x * 128;

    for (int i = tid; i < 96; i += 256) *(float*)(sm + SM_BIAS + i * 4) = b2[i];
    load_B_tile(sm, g_w2h, g_w2l, tid);
    load_A_tile(sm, g_o, row0, tid);
    __syncthreads();

    const int m0 = wid * 16;
    const u32 a_row = (u32)(m0 + (lane & 7) + ((lane >> 3) & 1) * 8);
    const u32 a_k   = (u32)((lane >> 4) * 8);
    const u32 aaddrH = sbase + SM_AH + a_row * SA_STRIDE + a_k * 2;
    const u32 aaddrL = sbase + SM_AL + a_row * SA_STRIDE + a_k * 2;
    const u32 b_row = (u32)((lane & 7) + ((lane >= 16) ? 8 : 0));
    const u32 b_k   = (u32)(((lane >> 3) & 1) * 8);
    const u32 baddrH = sbase + SM_BH + b_row * SA_STRIDE + b_k * 2;
    const u32 baddrL = sbase + SM_BL + b_row * SA_STRIDE + b_k * 2;

    float d[12][4];
    mma_slab(aaddrH, aaddrL, baddrH, baddrL, d);

    const int crow0 = m0 + lane / 4;
    const int ccol  = 2 * (lane & 3);
    float* dst0 = out + (size_t)(row0 + crow0) * EE;
    float* dst1 = out + (size_t)(row0 + crow0 + 8) * EE;
#pragma unroll
    for (int nc = 0; nc < 12; nc++) {
        int n = nc * 8 + ccol;
        float2 bv = *(const float2*)(sm + SM_BIAS + n * 4);
        *(float2*)(dst0 + n) = make_float2(d[nc][0] + bv.x, d[nc][1] + bv.y);
        *(float2*)(dst1 + n) = make_float2(d[nc][2] + bv.x, d[nc][3] + bv.y);
    }
}

// ---------------------------------------------------------------------------
// Kernel 2: windowed attention via mma.sync, term-major reordered loops.
// ---------------------------------------------------------------------------
#define AT_QH 0            // Q hi: 64 rows x 80B (40 halves, k-stride)
#define AT_QL 5120
#define AT_KH 10240
#define AT_KL 15360
#define AT_VH 20480        // Vt hi: 32 eh-rows x 144B (72 token-halves)
#define AT_VL 25088
#define AT_SZ 29696

__global__ __launch_bounds__(128) void attn_mma() {
    __shared__ unsigned char sm[AT_SZ];
    const u32 sbase = smem_u32(sm);
    const int tid = threadIdx.x, w = tid >> 5, lane = tid & 31;

    const int bw  = blockIdx.x;          // ((b*3 + H)*64 + win)
    const int win = bw % NWIN;
    const int xw  = win / 8, yw = win % 8;
    const int b   = bw / (NHh * NWIN);
    const int H   = (bw / NWIN) % NHh;

    // zero all smem (padding rows/cols must be 0)
    for (int i = tid; i < AT_SZ / 16; i += 128)
        ((float4*)sm)[i] = make_float4(0.f, 0.f, 0.f, 0.f);
    __syncthreads();

    // gather + convert + de-interleave: 49 tokens x 24 float4
    for (int i = tid; i < WWq * 24; i += 128) {
        int qi = i / 24, j = i % 24;
        int m1 = qi / WSw, m2 = qi - m1 * WSw;
        int h = xw * WSw + m1 + 4; if (h >= HHs) h -= HHs;   // inverse shift (-4 roll)
        int ww = yw * WSw + m2 + 4; if (ww >= HHs) ww -= HHs;
        float4 v4 = *(const float4*)(g_qkv + (size_t)(b * HWp + h * HHs + ww) * 288 + 96 * H + 4 * j);
        float vals[4] = {v4.x, v4.y, v4.z, v4.w};
#pragma unroll
        for (int dd = 0; dd < 4; dd++) {
            int c = 4 * j + dd;
            int e = c / 3, s = c - 3 * e;
            float v = vals[dd];
            __nv_bfloat16 hb = __float2bfloat16(v);
            __nv_bfloat16 lb = __float2bfloat16(v - __bfloat162float(hb));
            if (s == 0) {
                *(__nv_bfloat16*)(sm + AT_QH + qi * 80 + e * 2) = hb;
                *(__nv_bfloat16*)(sm + AT_QL + qi * 80 + e * 2) = lb;
            } else if (s == 1) {
                *(__nv_bfloat16*)(sm + AT_KH + qi * 80 + e * 2) = hb;
                *(__nv_bfloat16*)(sm + AT_KL + qi * 80 + e * 2) = lb;
            } else {
                *(__nv_bfloat16*)(sm + AT_VH + e * 144 + qi * 2) = hb;
                *(__nv_bfloat16*)(sm + AT_VL + e * 144 + qi * 2) = lb;
            }
        }
    }
    __syncthreads();

    // fragment addresses
    const u32 arow = (u32)(16 * w + (lane & 7) + 8 * ((lane >> 3) & 1));
    const u32 ak   = (u32)((lane >> 4) * 8);
    const u32 qaH = sbase + AT_QH + arow * 80 + ak * 2;
    const u32 qaL = sbase + AT_QL + arow * 80 + ak * 2;
    const u32 brow = (u32)((lane & 7) + ((lane >= 16) ? 8 : 0));
    const u32 bk   = (u32)(((lane >> 3) & 1) * 8);
    const u32 kaH = sbase + AT_KH + brow * 80 + bk * 2;
    const u32 kaL = sbase + AT_KL + brow * 80 + bk * 2;
    const u32 vaH = sbase + AT_VH + brow * 144 + bk * 2;
    const u32 vaL = sbase + AT_VL + brow * 144 + bk * 2;

    // Q fragments (k=32: 2 ksteps), hi and lo
    u32 qh[2][4], ql[2][4];
    LDSM4(qh[0], qaH);  LDSM4(qh[1], qaH + 32);
    LDSM4(ql[0], qaL);  LDSM4(ql[1], qaL + 32);

    // scores: 8 n-tiles (64 cols), 3-term compensation, term-major
    float d[8][4];
#pragma unroll
    for (int i = 0; i < 8; i++)
#pragma unroll
        for (int j = 0; j < 4; j++) d[i][j] = 0.f;
#pragma unroll
    for (int kt = 0; kt < 2; kt++) {
#pragma unroll
        for (int ng = 0; ng < 4; ng++) {           // term 1: Qh * Kh
            u32 kh[4];
            LDSM4(kh, kaH + (u32)ng * 16 * 80 + kt * 32);
            MMA_BF16(d[2 * ng],     qh[kt], kh[0], kh[1]);
            MMA_BF16(d[2 * ng + 1], qh[kt], kh[2], kh[3]);
        }
#pragma unroll
        for (int ng = 0; ng < 4; ng++) {           // term 2: Qh * Kl
            u32 kl[4];
            LDSM4(kl, kaL + (u32)ng * 16 * 80 + kt * 32);
            MMA_BF16(d[2 * ng],     qh[kt], kl[0], kl[1]);
            MMA_BF16(d[2 * ng + 1], qh[kt], kl[2], kl[3]);
        }
#pragma unroll
        for (int ng = 0; ng < 4; ng++) {           // term 3: Ql * Kh
            u32 kh[4];
            LDSM4(kh, kaH + (u32)ng * 16 * 80 + kt * 32);
            MMA_BF16(d[2 * ng],     ql[kt], kh[0], kh[1]);
            MMA_BF16(d[2 * ng + 1], ql[kt], kh[2], kh[3]);
        }
    }

    // scale + masks (faithful shift masks; ki>=49 padding masked out)
    const bool mrow = (xw == 7), mcol = (yw == 7);
    const int r0 = lane >> 2, c0 = 2 * (lane & 3);
    const int qia[2] = {16 * w + r0, 16 * w + r0 + 8};
#pragma unroll
    for (int half = 0; half < 2; half++) {
        int qi = qia[half];
        bool qr = (qi / WSw) >= 4;
        bool qc = (qi - WSw * (qi / WSw)) >= 4;
#pragma unroll
        for (int nt = 0; nt < 8; nt++) {
#pragma unroll
            for (int jj = 0; jj < 2; jj++) {
                int ki = 8 * nt + c0 + jj;
                float s = d[nt][2 * half + jj] * 0.17677669529663687f;
                if (ki >= WWq) s = -1e30f;
                else {
                    int km1 = ki / WSw, km2 = ki - WSw * km1;
                    if (mrow && ((km1 >= 4) != qr)) s = -1e30f;
                    if (mcol && ((km2 >= 4) != qc)) s = -1e30f;
                }
                d[nt][2 * half + jj] = s;
            }
        }
    }

    // softmax per row (row = lane-quad; reduce via xor 1,2)
#pragma unroll
    for (int half = 0; half < 2; half++) {
        float mx = -1e30f;
#pragma unroll
        for (int nt = 0; nt < 8; nt++)
            mx = fmaxf(mx, fmaxf(d[nt][2 * half], d[nt][2 * half + 1]));
        mx = fmaxf(mx, __shfl_xor_sync(0xffffffffu, mx, 1));
        mx = fmaxf(mx, __shfl_xor_sync(0xffffffffu, mx, 2));
        float sum = 0.f;
#pragma unroll
        for (int nt = 0; nt < 8; nt++) {
            float e0 = __expf(d[nt][2 * half] - mx);
            float e1 = __expf(d[nt][2 * half + 1] - mx);
            d[nt][2 * half] = e0; d[nt][2 * half + 1] = e1;
            sum += e0 + e1;
        }
        sum += __shfl_xor_sync(0xffffffffu, sum, 1);
        sum += __shfl_xor_sync(0xffffffffu, sum, 2);
        float inv = __frcp_rn(sum);
#pragma unroll
        for (int nt = 0; nt < 8; nt++) {
            d[nt][2 * half] *= inv; d[nt][2 * half + 1] *= inv;
        }
    }

    // P C-fragments -> bf16 hi/lo A-fragments (register identity, no smem)
    u32 ph[4][4], pl[4][4];
#pragma unroll
    for (int kt = 0; kt < 4; kt++) {
        cvt_pair(d[2 * kt][0],     d[2 * kt][1],     ph[kt][0], pl[kt][0]);
        cvt_pair(d[2 * kt][2],     d[2 * kt][3],     ph[kt][1], pl[kt][1]);
        cvt_pair(d[2 * kt + 1][0], d[2 * kt + 1][1], ph[kt][2], pl[kt][2]);
        cvt_pair(d[2 * kt + 1][2], d[2 * kt + 1][3], ph[kt][3], pl[kt][3]);
    }

    // PV: O[16 x 32], 4 ksteps x 2 eh-groups, 3-term, term-major
    float o[4][4];
#pragma unroll
    for (int i = 0; i < 4; i++)
#pragma unroll
        for (int j = 0; j < 4; j++) o[i][j] = 0.f;
#pragma unroll
    for (int kt = 0; kt < 4; kt++) {
#pragma unroll
        for (int ng = 0; ng < 2; ng++) {           // term 1: Ph * Vh
            u32 vh[4];
            LDSM4(vh, vaH + (u32)ng * 16 * 144 + kt * 32);
            MMA_BF16(o[2 * ng],     ph[kt], vh[0], vh[1]);
            MMA_BF16(o[2 * ng + 1], ph[kt], vh[2], vh[3]);
        }
#pragma unroll
        for (int ng = 0; ng < 2; ng++) {           // term 2: Ph * Vl
            u32 vl[4];
            LDSM4(vl, vaL + (u32)ng * 16 * 144 + kt * 32);
            MMA_BF16(o[2 * ng],     ph[kt], vl[0], vl[1]);
            MMA_BF16(o[2 * ng + 1], ph[kt], vl[2], vl[3]);
        }
#pragma unroll
        for (int ng = 0; ng < 2; ng++) {           // term 3: Pl * Vh
            u32 vh[4];
            LDSM4(vh, vaH + (u32)ng * 16 * 144 + kt * 32);
            MMA_BF16(o[2 * ng],     pl[kt], vh[0], vh[1]);
            MMA_BF16(o[2 * ng + 1], pl[kt], vh[2], vh[3]);
        }
    }

    // epilogue: reverse window partition + roll(+3)
#pragma unroll
    for (int half = 0; half < 2; half++) {
        int qi = qia[half];
        if (qi < WWq) {
            int m1 = qi / WSw, m2 = qi - WSw * m1;
            int h = (xw * WSw + m1 + 3) % HHs;
            int ww = (yw * WSw + m2 + 3) % HHs;
            float* dst = g_o + ((size_t)b * HWp + h * HHs + ww) * EE + H * EHh;
#pragma unroll
            for (int nt = 0; nt < 4; nt++)
                *(float2*)(dst + 8 * nt + c0) =
                    make_float2(o[nt][2 * half], o[nt][2 * half + 1]);
        }
    }
}

// ---------------------------------------------------------------------------
extern "C" void kernel_launch(void* const* d_in, const int* in_sizes, int n_in,
                              void* d_out, int out_size) {
    const float* x  = (const float*)d_in[0];
    const float* w1 = (const float*)d_in[1];
    const float* b1 = (const float*)d_in[2];
    const float* w2 = (const float*)d_in[3];
    const float* b2 = (const float*)d_in[4];
    float* out = (float*)d_out;

    cudaFuncSetAttribute(qkv_mma, cudaFuncAttributeMaxDynamicSharedMemorySize, SM_SZ);
    cudaFuncSetAttribute(proj_mma, cudaFuncAttributeMaxDynamicSharedMemorySize, SM_SZ);

    wconv_kernel<<<64, 256>>>(w1, w2);
    qkv_mma<<<BB * HWp / 128, 256, SM_SZ>>>(x, b1);
    attn_mma<<<BB * NHh * NWIN, 128>>>();
    proj_mma<<<BB * HWp / 128, 256, SM_SZ>>>(b2, out);
}

// round 15
// speedup vs baseline: 1.2282x; 1.2282x over previous
#include <cuda_runtime.h>
#include <cuda_fp16.h>
#include <cstdint>

// Problem constants
#define BB   128
#define HHs  56
#define HWp  3136
#define EE   96
#define NHh  3
#define EHh  32
#define WSw  7
#define NWIN 64
#define WWq  49

typedef unsigned long long ull;
typedef uint32_t u32;

// ---------------- mma.sync / ldmatrix helpers (sm_80+) ----------------
__device__ __forceinline__ u32 smem_u32(const void* p) {
    u32 a;
    asm("{ .reg .u64 t; cvta.to.shared.u64 t, %1; cvt.u32.u64 %0, t; }" : "=r"(a) : "l"(p));
    return a;
}
#define LDSM4(r, addr) \
    asm volatile("ldmatrix.sync.aligned.m8n8.x4.shared.b16 {%0,%1,%2,%3}, [%4];" \
        : "=r"((r)[0]), "=r"((r)[1]), "=r"((r)[2]), "=r"((r)[3]) : "r"(addr))
#define MMA_F16(d, a, b0, b1) \
    asm volatile("mma.sync.aligned.m16n8k16.row.col.f32.f16.f16.f32 " \
        "{%0,%1,%2,%3}, {%4,%5,%6,%7}, {%8,%9}, {%0,%1,%2,%3};" \
        : "+f"((d)[0]), "+f"((d)[1]), "+f"((d)[2]), "+f"((d)[3]) \
        : "r"((a)[0]), "r"((a)[1]), "r"((a)[2]), "r"((a)[3]), "r"(b0), "r"(b1))

// ---------------- scratch (allocation-free rule) ----------------
__device__ float g_qkv[(size_t)BB * HWp * 288];   // identity layout [row][288]
__device__ float g_o[(size_t)BB * HWp * EE];
// fp16 weights (single rounding), row-major [n][k], packed 2 halves per u32
__device__ __align__(16) u32 g_w1f[288 * 48];
__device__ __align__(16) u32 g_w2f[96 * 48];

// split fp32 pair -> fp16-hi pair + fp16-lo (residual) pair
__device__ __forceinline__ void cvt_pair_f16(float a, float b, u32& hp, u32& lp) {
    __half h0 = __float2half_rn(a), h1 = __float2half_rn(b);
    float f0 = __half2float(h0), f1 = __half2float(h1);
    __half l0 = __float2half_rn(a - f0), l1 = __float2half_rn(b - f1);
    hp = (u32)__half_as_ushort(h0) | ((u32)__half_as_ushort(h1) << 16);
    lp = (u32)__half_as_ushort(l0) | ((u32)__half_as_ushort(l1) << 16);
}
// single-rounded fp16 pair
__device__ __forceinline__ u32 cvt_single_f16(float a, float b) {
    return (u32)__half_as_ushort(__float2half_rn(a)) |
           ((u32)__half_as_ushort(__float2half_rn(b)) << 16);
}

__global__ __launch_bounds__(256) void wconv_kernel(const float* __restrict__ w1,
                                                    const float* __restrict__ w2) {
    int tid0 = blockIdx.x * 256 + threadIdx.x;
    int stride = gridDim.x * 256;
    for (int p = tid0; p < 288 * 48; p += stride) {
        int n = p / 48, kp = (p % 48) * 2;
        float2 v = *(const float2*)(w1 + (size_t)n * 96 + kp);
        g_w1f[p] = cvt_single_f16(v.x, v.y);
    }
    for (int p = tid0; p < 96 * 48; p += stride) {
        int n = p / 48, kp = (p % 48) * 2;
        float2 v = *(const float2*)(w2 + (size_t)n * 96 + kp);
        g_w2f[p] = cvt_single_f16(v.x, v.y);
    }
}

// ---------------- smem layout (GEMM kernels) ----------------
#define SA_STRIDE 208
#define SM_AH   0                  // 128 x 208B = 26624
#define SM_AL   26624              // -> 53248
#define SM_B    53248              // 96 x 208B = 19968 -> 73216
#define SM_BIAS 73216              // 288 floats -> 74368
#define SM_SZ   74368

__device__ __forceinline__ void load_A_tile(unsigned char* sm, const float* __restrict__ src,
                                            int row0, int tid) {
    for (int i = tid; i < 3072; i += 256) {
        int row = i / 24, k = (i % 24) * 4;
        float4 v = *(const float4*)(src + (size_t)(row0 + row) * EE + k);
        u32 hp0, lp0, hp1, lp1;
        cvt_pair_f16(v.x, v.y, hp0, lp0);
        cvt_pair_f16(v.z, v.w, hp1, lp1);
        u32 off = (u32)row * SA_STRIDE + (u32)k * 2;
        *(uint2*)(sm + SM_AH + off) = make_uint2(hp0, hp1);
        *(uint2*)(sm + SM_AL + off) = make_uint2(lp0, lp1);
    }
}
__device__ __forceinline__ void load_B_tile(unsigned char* sm, const u32* wf, int tid) {
    for (int i = tid; i < 1152; i += 256) {
        int row = i / 12, c4 = i % 12;
        *(float4*)(sm + SM_B + (u32)row * SA_STRIDE + c4 * 16) =
            ((const float4*)(wf + (size_t)row * 48))[c4];
    }
}

// 2-term fp16 compensated mainloop (np-major, R12-style ordering)
__device__ __forceinline__ void mma_slab(u32 aaddrH, u32 aaddrL, u32 baddr,
                                         float d[12][4]) {
#pragma unroll
    for (int i = 0; i < 12; i++)
#pragma unroll
        for (int j = 0; j < 4; j++) d[i][j] = 0.f;
#pragma unroll
    for (int ks = 0; ks < 6; ks++) {
        u32 ah[4], al[4];
        LDSM4(ah, aaddrH + ks * 32);
        LDSM4(al, aaddrL + ks * 32);
#pragma unroll
        for (int np = 0; np < 6; np++) {
            u32 bf[4];
            LDSM4(bf, baddr + (u32)np * 16 * SA_STRIDE + ks * 32);
            MMA_F16(d[2 * np],     ah, bf[0], bf[1]);
            MMA_F16(d[2 * np + 1], ah, bf[2], bf[3]);
            MMA_F16(d[2 * np],     al, bf[0], bf[1]);
            MMA_F16(d[2 * np + 1], al, bf[2], bf[3]);
        }
    }
}

// ---------------------------------------------------------------------------
// Kernel 1: qkv GEMM, 3 slabs per CTA. grid=3136. 3 CTAs/SM (74.4KB smem).
// ---------------------------------------------------------------------------
__global__ __launch_bounds__(256, 3) void qkv_mma(const float* __restrict__ x,
                                                  const float* __restrict__ b1) {
    extern __shared__ unsigned char sm[];
    const u32 sbase = smem_u32(sm);
    const int tid = threadIdx.x, wid = tid >> 5, lane = tid & 31;
    const int row0 = blockIdx.x * 128;

    for (int i = tid; i < 288; i += 256) *(float*)(sm + SM_BIAS + i * 4) = b1[i];
    load_A_tile(sm, x, row0, tid);

    const int m0 = wid * 16;
    const u32 a_row = (u32)(m0 + (lane & 7) + ((lane >> 3) & 1) * 8);
    const u32 a_k   = (u32)((lane >> 4) * 8);
    const u32 aaddrH = sbase + SM_AH + a_row * SA_STRIDE + a_k * 2;
    const u32 aaddrL = sbase + SM_AL + a_row * SA_STRIDE + a_k * 2;
    const u32 b_row = (u32)((lane & 7) + ((lane >= 16) ? 8 : 0));
    const u32 b_k   = (u32)(((lane >> 3) & 1) * 8);
    const u32 baddr = sbase + SM_B + b_row * SA_STRIDE + b_k * 2;
    const int crow0 = m0 + lane / 4;
    const int ccol  = 2 * (lane & 3);

#pragma unroll
    for (int nb = 0; nb < 3; nb++) {
        __syncthreads();
        load_B_tile(sm, g_w1f + (size_t)nb * 4608, tid);
        __syncthreads();

        float d[12][4];
        mma_slab(aaddrH, aaddrL, baddr, d);

        float* dst0 = g_qkv + (size_t)(row0 + crow0) * 288 + nb * 96;
        float* dst1 = g_qkv + (size_t)(row0 + crow0 + 8) * 288 + nb * 96;
#pragma unroll
        for (int nc = 0; nc < 12; nc++) {
            int n = nc * 8 + ccol;
            float2 bv = *(const float2*)(sm + SM_BIAS + (nb * 96 + n) * 4);
            *(float2*)(dst0 + n) = make_float2(d[nc][0] + bv.x, d[nc][1] + bv.y);
            *(float2*)(dst1 + n) = make_float2(d[nc][2] + bv.x, d[nc][3] + bv.y);
        }
    }
}

// ---------------------------------------------------------------------------
// Kernel 3: proj GEMM. grid=3136.
// ---------------------------------------------------------------------------
__global__ __launch_bounds__(256, 3) void proj_mma(const float* __restrict__ b2,
                                                   float* __restrict__ out) {
    extern __shared__ unsigned char sm[];
    const u32 sbase = smem_u32(sm);
    const int tid = threadIdx.x, wid = tid >> 5, lane = tid & 31;
    const int row0 = blockIdx.x * 128;

    for (int i = tid; i < 96; i += 256) *(float*)(sm + SM_BIAS + i * 4) = b2[i];
    load_B_tile(sm, g_w2f, tid);
    load_A_tile(sm, g_o, row0, tid);
    __syncthreads();

    const int m0 = wid * 16;
    const u32 a_row = (u32)(m0 + (lane & 7) + ((lane >> 3) & 1) * 8);
    const u32 a_k   = (u32)((lane >> 4) * 8);
    const u32 aaddrH = sbase + SM_AH + a_row * SA_STRIDE + a_k * 2;
    const u32 aaddrL = sbase + SM_AL + a_row * SA_STRIDE + a_k * 2;
    const u32 b_row = (u32)((lane & 7) + ((lane >= 16) ? 8 : 0));
    const u32 b_k   = (u32)(((lane >> 3) & 1) * 8);
    const u32 baddr = sbase + SM_B + b_row * SA_STRIDE + b_k * 2;

    float d[12][4];
    mma_slab(aaddrH, aaddrL, baddr, d);

    const int crow0 = m0 + lane / 4;
    const int ccol  = 2 * (lane & 3);
    float* dst0 = out + (size_t)(row0 + crow0) * EE;
    float* dst1 = out + (size_t)(row0 + crow0 + 8) * EE;
#pragma unroll
    for (int nc = 0; nc < 12; nc++) {
        int n = nc * 8 + ccol;
        float2 bv = *(const float2*)(sm + SM_BIAS + n * 4);
        *(float2*)(dst0 + n) = make_float2(d[nc][0] + bv.x, d[nc][1] + bv.y);
        *(float2*)(dst1 + n) = make_float2(d[nc][2] + bv.x, d[nc][3] + bv.y);
    }
}

// ---------------------------------------------------------------------------
// Kernel 2: windowed attention via mma.sync fp16 2-term.
// QK: Q split hi/lo, K single. PV: P single, V split hi/lo.
// ---------------------------------------------------------------------------
#define AT_QH 0            // Q hi: 64 rows x 80B
#define AT_QL 5120
#define AT_KF 10240        // K single fp16
#define AT_VH 15360        // Vt hi: 32 eh-rows x 144B
#define AT_VL 19968
#define AT_SZ 24576

__global__ __launch_bounds__(128) void attn_mma() {
    __shared__ unsigned char sm[AT_SZ];
    const u32 sbase = smem_u32(sm);
    const int tid = threadIdx.x, w = tid >> 5, lane = tid & 31;

    const int bw  = blockIdx.x;          // ((b*3 + H)*64 + win)
    const int win = bw % NWIN;
    const int xw  = win / 8, yw = win % 8;
    const int b   = bw / (NHh * NWIN);
    const int H   = (bw / NWIN) % NHh;

    // zero all smem (padding rows/cols must be 0)
    for (int i = tid; i < AT_SZ / 16; i += 128)
        ((float4*)sm)[i] = make_float4(0.f, 0.f, 0.f, 0.f);
    __syncthreads();

    // gather + convert + de-interleave: 49 tokens x 24 float4
    for (int i = tid; i < WWq * 24; i += 128) {
        int qi = i / 24, j = i % 24;
        int m1 = qi / WSw, m2 = qi - m1 * WSw;
        int h = xw * WSw + m1 + 4; if (h >= HHs) h -= HHs;   // inverse shift (-4 roll)
        int ww = yw * WSw + m2 + 4; if (ww >= HHs) ww -= HHs;
        float4 v4 = *(const float4*)(g_qkv + (size_t)(b * HWp + h * HHs + ww) * 288 + 96 * H + 4 * j);
        float vals[4] = {v4.x, v4.y, v4.z, v4.w};
#pragma unroll
        for (int dd = 0; dd < 4; dd++) {
            int c = 4 * j + dd;
            int e = c / 3, s = c - 3 * e;
            float v = vals[dd];
            if (s == 0) {
                __half hb = __float2half_rn(v);
                __half lb = __float2half_rn(v - __half2float(hb));
                *(__half*)(sm + AT_QH + qi * 80 + e * 2) = hb;
                *(__half*)(sm + AT_QL + qi * 80 + e * 2) = lb;
            } else if (s == 1) {
                *(__half*)(sm + AT_KF + qi * 80 + e * 2) = __float2half_rn(v);
            } else {
                __half hb = __float2half_rn(v);
                __half lb = __float2half_rn(v - __half2float(hb));
                *(__half*)(sm + AT_VH + e * 144 + qi * 2) = hb;
                *(__half*)(sm + AT_VL + e * 144 + qi * 2) = lb;
            }
        }
    }
    __syncthreads();

    // fragment addresses
    const u32 arow = (u32)(16 * w + (lane & 7) + 8 * ((lane >> 3) & 1));
    const u32 ak   = (u32)((lane >> 4) * 8);
    const u32 qaH = sbase + AT_QH + arow * 80 + ak * 2;
    const u32 qaL = sbase + AT_QL + arow * 80 + ak * 2;
    const u32 brow = (u32)((lane & 7) + ((lane >= 16) ? 8 : 0));
    const u32 bk   = (u32)(((lane >> 3) & 1) * 8);
    const u32 kaF = sbase + AT_KF + brow * 80 + bk * 2;
    const u32 vaH = sbase + AT_VH + brow * 144 + bk * 2;
    const u32 vaL = sbase + AT_VL + brow * 144 + bk * 2;

    // Q fragments (k=32: 2 ksteps), hi and lo
    u32 qh[2][4], ql[2][4];
    LDSM4(qh[0], qaH);  LDSM4(qh[1], qaH + 32);
    LDSM4(ql[0], qaL);  LDSM4(ql[1], qaL + 32);

    // scores: 8 n-tiles (64 cols), 2-term
    float d[8][4];
#pragma unroll
    for (int i = 0; i < 8; i++)
#pragma unroll
        for (int j = 0; j < 4; j++) d[i][j] = 0.f;
#pragma unroll
    for (int kt = 0; kt < 2; kt++) {
#pragma unroll
        for (int ng = 0; ng < 4; ng++) {
            u32 kf[4];
            LDSM4(kf, kaF + (u32)ng * 16 * 80 + kt * 32);
            MMA_F16(d[2 * ng],     qh[kt], kf[0], kf[1]);
            MMA_F16(d[2 * ng + 1], qh[kt], kf[2], kf[3]);
            MMA_F16(d[2 * ng],     ql[kt], kf[0], kf[1]);
            MMA_F16(d[2 * ng + 1], ql[kt], kf[2], kf[3]);
        }
    }

    // scale + masks (faithful shift masks; ki>=49 padding masked out)
    const bool mrow = (xw == 7), mcol = (yw == 7);
    const int r0 = lane >> 2, c0 = 2 * (lane & 3);
    const int qia[2] = {16 * w + r0, 16 * w + r0 + 8};
#pragma unroll
    for (int half = 0; half < 2; half++) {
        int qi = qia[half];
        bool qr = (qi / WSw) >= 4;
        bool qc = (qi - WSw * (qi / WSw)) >= 4;
#pragma unroll
        for (int nt = 0; nt < 8; nt++) {
#pragma unroll
            for (int jj = 0; jj < 2; jj++) {
                int ki = 8 * nt + c0 + jj;
                float s = d[nt][2 * half + jj] * 0.17677669529663687f;
                if (ki >= WWq) s = -1e30f;
                else {
                    int km1 = ki / WSw, km2 = ki - WSw * km1;
                    if (mrow && ((km1 >= 4) != qr)) s = -1e30f;
                    if (mcol && ((km2 >= 4) != qc)) s = -1e30f;
                }
                d[nt][2 * half + jj] = s;
            }
        }
    }

    // softmax per row (row = lane-quad; reduce via xor 1,2)
#pragma unroll
    for (int half = 0; half < 2; half++) {
        float mx = -1e30f;
#pragma unroll
        for (int nt = 0; nt < 8; nt++)
            mx = fmaxf(mx, fmaxf(d[nt][2 * half], d[nt][2 * half + 1]));
        mx = fmaxf(mx, __shfl_xor_sync(0xffffffffu, mx, 1));
        mx = fmaxf(mx, __shfl_xor_sync(0xffffffffu, mx, 2));
        float sum = 0.f;
#pragma unroll
        for (int nt = 0; nt < 8; nt++) {
            float e0 = __expf(d[nt][2 * half] - mx);
            float e1 = __expf(d[nt][2 * half + 1] - mx);
            d[nt][2 * half] = e0; d[nt][2 * half + 1] = e1;
            sum += e0 + e1;
        }
        sum += __shfl_xor_sync(0xffffffffu, sum, 1);
        sum += __shfl_xor_sync(0xffffffffu, sum, 2);
        float inv = __frcp_rn(sum);
#pragma unroll
        for (int nt = 0; nt < 8; nt++) {
            d[nt][2 * half] *= inv; d[nt][2 * half + 1] *= inv;
        }
    }

    // P C-fragments -> single fp16 A-fragments (register identity, no smem)
    u32 pf[4][4];
#pragma unroll
    for (int kt = 0; kt < 4; kt++) {
        pf[kt][0] = cvt_single_f16(d[2 * kt][0],     d[2 * kt][1]);
        pf[kt][1] = cvt_single_f16(d[2 * kt][2],     d[2 * kt][3]);
        pf[kt][2] = cvt_single_f16(d[2 * kt + 1][0], d[2 * kt + 1][1]);
        pf[kt][3] = cvt_single_f16(d[2 * kt + 1][2], d[2 * kt + 1][3]);
    }

    // PV: O[16 x 32], 4 ksteps x 2 eh-groups, 2-term (V split)
    float o[4][4];
#pragma unroll
    for (int i = 0; i < 4; i++)
#pragma unroll
        for (int j = 0; j < 4; j++) o[i][j] = 0.f;
#pragma unroll
    for (int kt = 0; kt < 4; kt++) {
#pragma unroll
        for (int ng = 0; ng < 2; ng++) {
            u32 vh[4], vl[4];
            LDSM4(vh, vaH + (u32)ng * 16 * 144 + kt * 32);
            LDSM4(vl, vaL + (u32)ng * 16 * 144 + kt * 32);
            MMA_F16(o[2 * ng],     pf[kt], vh[0], vh[1]);
            MMA_F16(o[2 * ng + 1], pf[kt], vh[2], vh[3]);
            MMA_F16(o[2 * ng],     pf[kt], vl[0], vl[1]);
            MMA_F16(o[2 * ng + 1], pf[kt], vl[2], vl[3]);
        }
    }

    // epilogue: reverse window partition + roll(+3)
#pragma unroll
    for (int half = 0; half < 2; half++) {
        int qi = qia[half];
        if (qi < WWq) {
            int m1 = qi / WSw, m2 = qi - WSw * m1;
            int h = (xw * WSw + m1 + 3) % HHs;
            int ww = (yw * WSw + m2 + 3) % HHs;
            float* dst = g_o + ((size_t)b * HWp + h * HHs + ww) * EE + H * EHh;
#pragma unroll
            for (int nt = 0; nt < 4; nt++)
                *(float2*)(dst + 8 * nt + c0) =
                    make_float2(o[nt][2 * half], o[nt][2 * half + 1]);
        }
    }
}

// ---------------------------------------------------------------------------
extern "C" void kernel_launch(void* const* d_in, const int* in_sizes, int n_in,
                              void* d_out, int out_size) {
    const float* x  = (const float*)d_in[0];
    const float* w1 = (const float*)d_in[1];
    const float* b1 = (const float*)d_in[2];
    const float* w2 = (const float*)d_in[3];
    const float* b2 = (const float*)d_in[4];
    float* out = (float*)d_out;

    cudaFuncSetAttribute(qkv_mma, cudaFuncAttributeMaxDynamicSharedMemorySize, SM_SZ);
    cudaFuncSetAttribute(proj_mma, cudaFuncAttributeMaxDynamicSharedMemorySize, SM_SZ);

    wconv_kernel<<<64, 256>>>(w1, w2);
    qkv_mma<<<BB * HWp / 128, 256, SM_SZ>>>(x, b1);
    attn_mma<<<BB * NHh * NWIN, 128>>>();
    proj_mma<<<BB * HWp / 128, 256, SM_SZ>>>(b2, out);
}